// round 17
// baseline (speedup 1.0000x reference)
#include <cuda_runtime.h>
#include <math.h>
#include <stdint.h>

// Shapes (fixed by the problem)
#define BB   4
#define NN   2048
#define DD   1024
#define DLL  64
#define DKK  128
#define DCC  8
#define NT   128            // n-tiles of 16 rows

// -------- device scratch (static: no allocations allowed) --------
__device__ float g_lam[BB];
__device__ float g_q[BB*DKK];        // q / tau
__device__ float g_qB[BB*DCC*DKK];   // (q/tau)^T basis_r
__device__ float g_u[BB*9*DD];       // u_0 = W_K^T (q/tau); u_r = W_K^T qB_r
__device__ float g_yp[NT*BB*DD];     // partial numerators N_b[d] per n-tile
__device__ float g_pm[NT*BB];        // per-tile max
__device__ float g_pz[NT*BB];        // per-tile sum-exp (no screen)
__device__ float g_y[BB*DD];         // combined, scaled y
__device__ float g_av[BB*DKK];       // av = W_V y

// -------- software grid barrier (generation-based; survives replays) --------
__device__ unsigned g_bar_cnt;
__device__ volatile unsigned g_bar_gen;

__device__ __forceinline__ void gbar() {
    __syncthreads();
    if (threadIdx.x == 0) {
        __threadfence();
        unsigned gen = g_bar_gen;
        if (atomicAdd(&g_bar_cnt, 1u) == gridDim.x - 1) {
            g_bar_cnt = 0;
            __threadfence();
            g_bar_gen = gen + 1;
        } else {
            while (g_bar_gen == gen) __nanosleep(64);
        }
        __threadfence();
    }
    __syncthreads();
}

// ================= single persistent kernel: all 7 phases =================
__global__ void __launch_bounds__(256) k_all(
    const float* __restrict__ xq, const float* __restrict__ zq,
    const float* __restrict__ xk, const float* __restrict__ zk,
    const float* __restrict__ WQ, const float* __restrict__ WQz,
    const float* __restrict__ WQg, const float* __restrict__ WK,
    const float* __restrict__ WV, const float* __restrict__ WO,
    const float* __restrict__ Wd,
    const float* __restrict__ bb, const float* __restrict__ be,
    const float* __restrict__ bo, const float* __restrict__ logsig,
    float* __restrict__ out) {

    __shared__ float sm[9728];            // 38 KB union across phases
    const int t = threadIdx.x;

    // ---------- P1: q[b,a] (scaled by 1/tau) — 512 units ----------
    for (int u_ = blockIdx.x; u_ < 512; u_ += gridDim.x) {
        int a = u_ & 127, b = u_ >> 7;
        float* zs = sm;                   // 64
        float* red = sm + 64;             // 256
        if (t < DLL) zs[t] = zq[b*DLL + t];
        __syncthreads();
        float4 wv = ((const float4*)(WQ + (size_t)a*DD))[t];
        float4 xv = ((const float4*)(xq + (size_t)b*DD))[t];
        float s = wv.x*xv.x + wv.y*xv.y + wv.z*xv.z + wv.w*xv.w;
        if (t < DLL) s += zs[t]*WQz[a*DLL + t];
        const float* G = WQg + (size_t)a*DLL*DLL;
        #pragma unroll 4
        for (int idx = t; idx < DLL*DLL; idx += 256)
            s += G[idx]*zs[idx >> 6]*zs[idx & 63];
        red[t] = s; __syncthreads();
        for (int o = 128; o; o >>= 1) { if (t < o) red[t] += red[t+o]; __syncthreads(); }
        if (t == 0) {
            float rsq = 0.f;
            for (int l = 0; l < DLL; l++) rsq += zs[l]*zs[l];
            rsq = fminf(rsq, 1.f - 1e-6f);
            float lam = 2.f/(1.f - rsq + 1e-6f);
            g_q[b*DKK + a] = red[0] * lam / sqrtf((float)DKK);
            if (a == 0) g_lam[b] = lam;
        }
        __syncthreads();
    }
    gbar();

    // ---------- P2: qB[b,r,j] — 32 units ----------
    for (int u_ = blockIdx.x; u_ < 32; u_ += gridDim.x) {
        int r = u_ & 7, b = u_ >> 3;
        const float* Bb = bb + ((size_t)r << 14);
        const float* Be = be + ((size_t)r << 14);
        const float* Bo = bo + ((size_t)r << 14);
        int j = t & 127, h = t >> 7;      // 2 i-halves of 64
        float* qs = sm;                   // 128
        float* red = sm + 128;            // 256
        if (t < DKK) qs[t] = g_q[b*DKK + t];
        __syncthreads();
        float acc = 0.f;
        #pragma unroll 4
        for (int i = h*64; i < h*64 + 64; i++) {
            int ij = i*DKK + j, ji = j*DKK + i;
            float gij = Bb[ij] + 0.5f*Be[ij] + 0.3f*Bo[ij];
            float gji = Bb[ji] + 0.5f*Be[ji] + 0.3f*Bo[ji];
            acc += qs[i]*(gij - gji);
        }
        red[t] = acc; __syncthreads();
        if (t < DKK) g_qB[(b*DCC + r)*DKK + j] = red[j] + red[128 + j];
        __syncthreads();
    }
    gbar();

    // ---------- P3: U[b,r,d] — 128 units ----------
    for (int u_ = blockIdx.x; u_ < 128; u_ += gridDim.x) {
        int dt = u_ & 31, b = u_ >> 5;
        int d = dt*32 + (t & 31);
        int isl = t >> 5;                 // 8 i-slices of 16
        float* e = sm;                    // 1152
        float* red = sm + 1152;           // 2304
        for (int idx = t; idx < 9*DKK; idx += 256)
            e[idx] = (idx < DKK) ? g_q[b*DKK + idx] : g_qB[b*DCC*DKK + idx - DKK];
        __syncthreads();
        float acc[9];
        #pragma unroll
        for (int r = 0; r < 9; r++) acc[r] = 0.f;
        #pragma unroll
        for (int i = isl*16; i < isl*16 + 16; i++) {
            float w = WK[(size_t)i*DD + d];
            #pragma unroll
            for (int r = 0; r < 9; r++) acc[r] += e[r*DKK + i]*w;
        }
        #pragma unroll
        for (int r = 0; r < 9; r++) red[(r*8 + isl)*32 + (t & 31)] = acc[r];
        __syncthreads();
        for (int o = t; o < 9*32; o += 256) {
            int r = o >> 5, dd = o & 31;
            float s = 0.f;
            #pragma unroll
            for (int k = 0; k < 8; k++) s += red[(r*8 + k)*32 + dd];
            g_u[b*9*DD + r*DD + dt*32 + dd] = s;
        }
        __syncthreads();
    }
    gbar();

    // ---------- P4: fused scores + screening + partial softmax-y — 512 units ----------
    for (int u_ = blockIdx.x; u_ < 512; u_ += gridDim.x) {
        int nt = u_ >> 2, b = u_ & 3;
        int n0 = nt * 16;
        int warp = t >> 5, lane = t & 31;
        float* su = sm;                   // 9216
        float* scoefp = sm + 9216;        // 16*8 = 128
        float* sdist  = sm + 9344;        // 16
        float* szq    = sm + 9360;        // 64
        float* sscore = sm + 9424;        // 16
        float* sw     = sm + 9440;        // 16

        {
            const float4* src = (const float4*)(g_u + (size_t)b*9*DD);
            float4* dst = (float4*)su;
            #pragma unroll
            for (int i = 0; i < 9; i++) dst[t + i*256] = src[t + i*256];
        }
        if (t < DLL) szq[t] = zq[b*DLL + t];
        __syncthreads();

        #pragma unroll
        for (int rr = 0; rr < 2; rr++) {
            int row = warp*2 + rr;
            int n = n0 + row;
            const float* zkp = zk + ((size_t)b*NN + n)*DLL;
            float d0 = szq[lane] - zkp[lane];
            float d1 = szq[lane+32] - zkp[lane+32];
            float dist = d0*d0 + d1*d1;
            #pragma unroll
            for (int o = 16; o; o >>= 1) dist += __shfl_xor_sync(0xffffffffu, dist, o);
            if (lane == 0) sdist[row] = dist;
            #pragma unroll
            for (int r = 0; r < DCC; r++) {
                float p = d0*Wd[r*DLL + lane] + d1*Wd[r*DLL + 32 + lane];
                #pragma unroll
                for (int o = 16; o; o >>= 1) p += __shfl_xor_sync(0xffffffffu, p, o);
                if (lane == 0) scoefp[row*DCC + r] = p;
            }
        }
        __syncthreads();

        float lam = g_lam[b];
        float sfac = -expf(logsig[0]) * 0.5f * lam * lam;

        int row0 = warp*2;
        int n = n0 + row0;
        const float4* xp = (const float4*)(xk + ((size_t)b*NN + n)*DD);
        const float4* su4 = (const float4*)su;
        float acc[2][9];
        #pragma unroll
        for (int i = 0; i < 2; i++)
            #pragma unroll
            for (int r = 0; r < 9; r++) acc[i][r] = 0.f;
        #pragma unroll
        for (int k = 0; k < 8; k++) {
            int dk = lane + 32*k;
            float4 x0 = xp[dk];
            float4 x1 = xp[256 + dk];
            #pragma unroll
            for (int g = 0; g < 3; g++) {
                float4 u0 = su4[(3*g+0)*256 + dk];
                float4 u1 = su4[(3*g+1)*256 + dk];
                float4 u2 = su4[(3*g+2)*256 + dk];
                acc[0][3*g+0] += x0.x*u0.x + x0.y*u0.y + x0.z*u0.z + x0.w*u0.w;
                acc[1][3*g+0] += x1.x*u0.x + x1.y*u0.y + x1.z*u0.z + x1.w*u0.w;
                acc[0][3*g+1] += x0.x*u1.x + x0.y*u1.y + x0.z*u1.z + x0.w*u1.w;
                acc[1][3*g+1] += x1.x*u1.x + x1.y*u1.y + x1.z*u1.z + x1.w*u1.w;
                acc[0][3*g+2] += x0.x*u2.x + x0.y*u2.y + x0.z*u2.z + x0.w*u2.w;
                acc[1][3*g+2] += x1.x*u2.x + x1.y*u2.y + x1.z*u2.z + x1.w*u2.w;
            }
        }
        #pragma unroll
        for (int i = 0; i < 2; i++)
            #pragma unroll
            for (int r = 0; r < 9; r++) {
                #pragma unroll
                for (int o = 16; o; o >>= 1)
                    acc[i][r] += __shfl_xor_sync(0xffffffffu, acc[i][r], o);
            }
        if (lane == 0) {
            #pragma unroll
            for (int i = 0; i < 2; i++) {
                float s = acc[i][0];
                #pragma unroll
                for (int r = 0; r < 8; r++) s += scoefp[(row0+i)*DCC + r] * acc[i][r+1];
                sscore[row0 + i] = s;
            }
        }
        __syncthreads();

        if (t == 0) {
            float m = -1e30f;
            #pragma unroll
            for (int i = 0; i < 16; i++) m = fmaxf(m, sscore[i]);
            float Z = 0.f;
            #pragma unroll
            for (int i = 0; i < 16; i++) {
                float e = expf(sscore[i] - m);
                Z += e;
                sw[i] = e * expf(sfac * sdist[i]);
            }
            g_pm[nt*BB + b] = m;
            g_pz[nt*BB + b] = Z;
        }
        __syncthreads();

        const float4* xb = (const float4*)(xk + ((size_t)b*NN + n0)*DD);
        float4 ya = make_float4(0.f, 0.f, 0.f, 0.f);
        #pragma unroll
        for (int row = 0; row < 16; row++) {
            float wv = sw[row];
            float4 xv = xb[row*256 + t];
            ya.x += wv*xv.x; ya.y += wv*xv.y; ya.z += wv*xv.z; ya.w += wv*xv.w;
        }
        *(float4*)(g_yp + (size_t)(nt*BB + b)*DD + t*4) = ya;
        __syncthreads();
    }
    gbar();

    // ---------- P5: combine partials -> scaled y — 128 units ----------
    for (int u_ = blockIdx.x; u_ < 128; u_ += gridDim.x) {
        int dt = u_ & 31, b = u_ >> 5;
        float* sscale = sm;               // 128
        float* red = sm + 128;            // 256
        float mv = (t < NT) ? g_pm[t*BB + b] : -1e30f;
        red[t] = mv; __syncthreads();
        for (int o = 128; o; o >>= 1) { if (t < o) red[t] = fmaxf(red[t], red[t+o]); __syncthreads(); }
        float M = red[0]; __syncthreads();
        float ez = 0.f;
        if (t < NT) {
            float e = expf(g_pm[t*BB + b] - M);
            sscale[t] = e;
            ez = e * g_pz[t*BB + b];
        }
        red[t] = ez; __syncthreads();
        for (int o = 128; o; o >>= 1) { if (t < o) red[t] += red[t+o]; __syncthreads(); }
        float Sinv = 1.f / red[0];
        __syncthreads();
        int dl = t & 31, strip = t >> 5;  // 8 strips of 16 partials
        int d = dt*32 + dl;
        float acc = 0.f;
        #pragma unroll
        for (int pp = 0; pp < 16; pp++) {
            int p = strip*16 + pp;
            acc += sscale[p] * g_yp[(size_t)(p*BB + b)*DD + d];
        }
        red[t] = acc; __syncthreads();
        if (strip == 0) {
            float s = 0.f;
            #pragma unroll
            for (int k = 0; k < 8; k++) s += red[dl + k*32];
            g_y[b*DD + d] = s * Sinv;
        }
        __syncthreads();
    }
    gbar();

    // ---------- P6: av[b,a] = y . WV[a,:] — 512 units ----------
    for (int u_ = blockIdx.x; u_ < 512; u_ += gridDim.x) {
        int a = u_ & 127, b = u_ >> 7;
        float* red = sm;
        float4 w = ((const float4*)(WV + (size_t)a*DD))[t];
        float4 y = ((const float4*)(g_y + (size_t)b*DD))[t];
        float s = w.x*y.x + w.y*y.y + w.z*y.z + w.w*y.w;
        red[t] = s; __syncthreads();
        for (int o = 128; o; o >>= 1) { if (t < o) red[t] += red[t+o]; __syncthreads(); }
        if (t == 0) g_av[b*DKK + a] = red[0];
        __syncthreads();
    }
    gbar();

    // ---------- P7: out[b,d] = av . WO[d,:] — 16 units ----------
    for (int u_ = blockIdx.x; u_ < 16; u_ += gridDim.x) {
        int dt = u_ & 3, b = u_ >> 2;
        float* av = sm;
        if (t < DKK) av[t] = g_av[b*DKK + t];
        __syncthreads();
        int d = dt*256 + t;
        float s = 0.f;
        const float4* wo = (const float4*)(WO + (size_t)d*DKK);
        #pragma unroll 8
        for (int a4 = 0; a4 < 32; a4++) {
            float4 wv = wo[a4];
            s += av[a4*4+0]*wv.x + av[a4*4+1]*wv.y + av[a4*4+2]*wv.z + av[a4*4+3]*wv.w;
        }
        out[b*DD + d] = s;
        __syncthreads();
    }
}

extern "C" void kernel_launch(void* const* d_in, const int* in_sizes, int n_in,
                              void* d_out, int out_size) {
    const float* x_query   = (const float*)d_in[0];
    const float* z_query   = (const float*)d_in[1];
    const float* x_keys    = (const float*)d_in[2];
    const float* z_keys    = (const float*)d_in[3];
    const float* W_Q       = (const float*)d_in[4];
    const float* W_Qz      = (const float*)d_in[5];
    const float* W_Qg      = (const float*)d_in[6];
    const float* W_K       = (const float*)d_in[7];
    const float* W_V       = (const float*)d_in[8];
    const float* W_O       = (const float*)d_in[9];
    const float* W_delta   = (const float*)d_in[10];
    const float* basis_b   = (const float*)d_in[11];
    const float* basis_e   = (const float*)d_in[12];
    const float* basis_o   = (const float*)d_in[13];
    const float* log_sigma = (const float*)d_in[14];
    float* out = (float*)d_out;

    // Residency-safe grid: occupancy-derived, phases use grid-stride loops.
    cudaFuncSetAttribute(k_all, cudaFuncAttributePreferredSharedMemoryCarveout, 100);
    int mb = 0, nsm = 0, dev = 0;
    cudaGetDevice(&dev);
    cudaDeviceGetAttribute(&nsm, cudaDevAttrMultiProcessorCount, dev);
    cudaOccupancyMaxActiveBlocksPerMultiprocessor(&mb, k_all, 256, 0);
    if (mb < 1) mb = 1;
    if (nsm < 1) nsm = 148;
    int grid = mb * nsm;
    if (grid > 512) grid = 512;

    k_all<<<grid, 256>>>(x_query, z_query, x_keys, z_keys,
                         W_Q, W_Qz, W_Qg, W_K, W_V, W_O, W_delta,
                         basis_b, basis_e, basis_o, log_sigma, out);
}